// round 3
// baseline (speedup 1.0000x reference)
#include <cuda_runtime.h>

// SurfEval: NURBS surface evaluation.
// B=8, M=N=64, P=Q=3, GRID=512, DIM=3.
// Inputs: ctrl_pts [B,M,N,4], uspan [G], vspan [G], Nu [G,4], Nv [G,4]
// Output: float32 [B, G, G, 3]
//
// R3 design: 4 g-rows per CTA, 4 h-points per thread, direct coalesced
// float4 stores (no row staging), single barrier, operand hoisting.

#define BB    8
#define MM    64
#define NN    64
#define GRIDD 512
#define RPC   4          // rows (g values) per CTA
#define PPT   4          // points (h values) per thread

__global__ __launch_bounds__(512)
void surf_eval_kernel(const float* __restrict__ ctrl,
                      const int*   __restrict__ uspan,
                      const int*   __restrict__ vspan,
                      const float* __restrict__ Nu,
                      const float* __restrict__ Nv,
                      float*       __restrict__ out)
{
    __shared__ float su_s[RPC * NN * 4];   // 4 rows of Su[n][d], 4 KB

    const int g0 = blockIdx.x * RPC;       // first u row of this CTA
    const int b  = blockIdx.y;
    const int t  = threadIdx.x;            // 0..511

    // ---- Hoisted Phase-2 operands (overlap their latency with Phase 1) ----
    const int irow = t >> 7;               // which row this thread evaluates
    const int i    = t & 127;              // lane within row
    const int h0   = i * PPT;              // first h of this thread

    const int4 sv4 = *reinterpret_cast<const int4*>(vspan + h0);
    float4 nv[PPT];
    #pragma unroll
    for (int p = 0; p < PPT; p++)
        nv[p] = *reinterpret_cast<const float4*>(Nv + 4 * (h0 + p));

    // ---- Phase 1: u-contraction for 4 rows into shared memory ----
    // 4 rows x 256 (n,d)-slots = 1024 values; each thread computes 2.
    #pragma unroll
    for (int k = t; k < RPC * NN * 4; k += 512) {
        const int row = k >> 8;            // 0..3
        const int j   = k & 255;           // flattened (n,d)
        const int    su = uspan[g0 + row];
        const float4 nu = *reinterpret_cast<const float4*>(Nu + 4 * (g0 + row));
        const float* base = ctrl + ((size_t)b * MM + (su - 3)) * (NN * 4);
        su_s[k] = nu.x * base[j]
                + nu.y * base[j + 1 * NN * 4]
                + nu.z * base[j + 2 * NN * 4]
                + nu.w * base[j + 3 * NN * 4];
    }
    __syncthreads();

    // ---- Phase 2: v-contraction, 4 consecutive points per thread ----
    const float* su_row = su_s + irow * (NN * 4);
    const int svv[PPT] = { sv4.x, sv4.y, sv4.z, sv4.w };

    float xr[PPT], yr[PPT], zr[PPT];
    #pragma unroll
    for (int p = 0; p < PPT; p++) {
        const int sv = svv[p];
        const float4 p0 = *reinterpret_cast<const float4*>(su_row + 4 * (sv - 3));
        const float4 p1 = *reinterpret_cast<const float4*>(su_row + 4 * (sv - 2));
        const float4 p2 = *reinterpret_cast<const float4*>(su_row + 4 * (sv - 1));
        const float4 p3 = *reinterpret_cast<const float4*>(su_row + 4 * (sv - 0));
        const float4 c  = nv[p];

        float x = c.x * p0.x + c.y * p1.x + c.z * p2.x + c.w * p3.x;
        float y = c.x * p0.y + c.y * p1.y + c.z * p2.y + c.w * p3.y;
        float z = c.x * p0.z + c.y * p1.z + c.z * p2.z + c.w * p3.z;
        float w = c.x * p0.w + c.y * p1.w + c.z * p2.w + c.w * p3.w;

        const float inv = 1.0f / w;
        xr[p] = x * inv;  yr[p] = y * inv;  zr[p] = z * inv;
    }

    // ---- Direct coalesced stores: 4 points x 3 floats = 3 float4 ----
    // Row base is 6144-byte aligned; h0*3*4 = i*48 bytes -> 16B aligned.
    float* orow = out + (((size_t)b * GRIDD + (g0 + irow)) * GRIDD + h0) * 3;
    reinterpret_cast<float4*>(orow)[0] = make_float4(xr[0], yr[0], zr[0], xr[1]);
    reinterpret_cast<float4*>(orow)[1] = make_float4(yr[1], zr[1], xr[2], yr[2]);
    reinterpret_cast<float4*>(orow)[2] = make_float4(zr[2], xr[3], yr[3], zr[3]);
}

extern "C" void kernel_launch(void* const* d_in, const int* in_sizes, int n_in,
                              void* d_out, int out_size)
{
    const float* ctrl  = (const float*)d_in[0];
    const int*   uspan = (const int*)  d_in[1];
    const int*   vspan = (const int*)  d_in[2];
    const float* Nu    = (const float*)d_in[3];
    const float* Nv    = (const float*)d_in[4];
    float*       out   = (float*)d_out;

    dim3 grid(GRIDD / RPC, BB);   // 128 x 8 = 1024 CTAs
    surf_eval_kernel<<<grid, 512>>>(ctrl, uspan, vspan, Nu, Nv, out);
}